// round 14
// baseline (speedup 1.0000x reference)
#include <cuda_runtime.h>
#include <cuda_bf16.h>
#include <cstdint>
#include <cstddef>

#define BATCH 256
#define SEQ 145
#define DM 388
#define DI 776
#define DS 16
#define DC 4
#define DR 25
#define NB 5
#define TOK (BATCH*SEQ)          /* 37120 */
#define XPO (DR + 2*DS)          /* 57 */
#define FLAT (SEQ*DM)            /* 56260 */

// padded K (before 3x split concat) and padded N per GEMM
#define KP_IN  448
#define NP_IN  1664
#define KP_XP  832
#define NP_XP  128
#define K3_DT  128               /* tight: [Ah(25)|Ah(25)|Al(25)|0(53)] */
#define NP_DT  896
#define KP_OUT 832
#define NP_OUT 512
#define MAXK3  (3*832)           /* 2496 */

// ---------------- scratch ----------------
__device__ float g_xz [TOK*2*DI];
__device__ float g_xc [TOK*DI];
__device__ float g_dbl[TOK*XPO];
__device__ float g_dt [TOK*DI];
__device__ float g_x  [TOK*DM];
__device__ __nv_bfloat16 g_a3[(size_t)TOK*MAXK3];       // split activations [TOK, 3*Kp]
__device__ __nv_bfloat16 g_adt[(size_t)TOK*K3_DT];      // dt split
__device__ __nv_bfloat16 g_b3[(size_t)NP_IN*3*KP_IN];   // split weights (max 1664*1344)

// ---------------- helpers ----------------
__device__ __forceinline__ uint32_t smem_u32(const void* p) {
    uint32_t a;
    asm("{ .reg .u64 t; cvta.to.shared.u64 t, %1; cvt.u32.u64 %0, t; }" : "=r"(a) : "l"(p));
    return a;
}
__device__ __forceinline__ void cpasync16(uint32_t s, const void* g) {
    asm volatile("cp.async.cg.shared.global [%0], [%1], 16;" :: "r"(s), "l"(g));
}
__device__ __forceinline__ void ldsm4(uint32_t* r, uint32_t a) {
    asm volatile("ldmatrix.sync.aligned.m8n8.x4.shared.b16 {%0,%1,%2,%3}, [%4];"
                 : "=r"(r[0]), "=r"(r[1]), "=r"(r[2]), "=r"(r[3]) : "r"(a));
}
__device__ __forceinline__ void ldsm2(uint32_t* r, uint32_t a) {
    asm volatile("ldmatrix.sync.aligned.m8n8.x2.shared.b16 {%0,%1}, [%2];"
                 : "=r"(r[0]), "=r"(r[1]) : "r"(a));
}
__device__ __forceinline__ void mma16816(float* d, const uint32_t* a, const uint32_t* b) {
    asm volatile("mma.sync.aligned.m16n8k16.row.col.f32.bf16.bf16.f32 "
                 "{%0,%1,%2,%3}, {%4,%5,%6,%7}, {%8,%9}, {%0,%1,%2,%3};"
                 : "+f"(d[0]), "+f"(d[1]), "+f"(d[2]), "+f"(d[3])
                 : "r"(a[0]), "r"(a[1]), "r"(a[2]), "r"(a[3]), "r"(b[0]), "r"(b[1]));
}
__device__ __forceinline__ void split_bf16(float v, __nv_bfloat16& h, __nv_bfloat16& l) {
    h = __float2bfloat16(v);
    l = __float2bfloat16(v - __bfloat162float(h));
}
__device__ __forceinline__ uint32_t pack2(__nv_bfloat16 a, __nv_bfloat16 b) {
    __nv_bfloat162 t = __halves2bfloat162(a, b);
    return *reinterpret_cast<uint32_t*>(&t);
}

// ---------------- bf16 HMMA GEMM (3-stage cp.async pipeline, 2 CTA/SM) ----------------
// EXACT R12 version (7.50 ms config). C[M,N] = A3[M,K3] x B3[Np,K3]^T, fp32 accum.
__global__ void __launch_bounds__(256, 2)
mma_gemm(const __nv_bfloat16* __restrict__ A, const __nv_bfloat16* __restrict__ B, int K3,
         float* __restrict__ C, int sC, int N,
         const float* __restrict__ bias, int act) {
    extern __shared__ char smem[];
    uint32_t sb = smem_u32(smem);
    const uint32_t SAo[3] = {0, 32768, 65536};
    const uint32_t SBo[3] = {16384, 49152, 81920};
    int tid = threadIdx.x, wid = tid >> 5, lane = tid & 31;
    int wm = wid & 1, wn = wid >> 1;          // 2 x 4 warp grid
    int m0 = blockIdx.x * 128, n0 = blockIdx.y * 128;

    int lrow[4], lc[4];
    uint32_t lso[4];
    #pragma unroll
    for (int j = 0; j < 4; j++) {
        int cid = tid + j * 256;
        lrow[j] = cid >> 3;
        lc[j] = cid & 7;
        lso[j] = (uint32_t)(lrow[j] * 128 + ((lc[j] ^ (lrow[j] & 7)) * 16));
    }

    auto prefetch = [&](int k0, int st) {
        #pragma unroll
        for (int j = 0; j < 4; j++) {
            const __nv_bfloat16* ga = A + (size_t)(m0 + lrow[j]) * K3 + k0 + lc[j] * 8;
            const __nv_bfloat16* gb = B + (size_t)(n0 + lrow[j]) * K3 + k0 + lc[j] * 8;
            cpasync16(sb + SAo[st] + lso[j], ga);
            cpasync16(sb + SBo[st] + lso[j], gb);
        }
        asm volatile("cp.async.commit_group;" ::: "memory");
    };

    float acc[4][4][4];
    #pragma unroll
    for (int i = 0; i < 4; i++)
        #pragma unroll
        for (int j = 0; j < 4; j++)
            #pragma unroll
            for (int r = 0; r < 4; r++) acc[i][j][r] = 0.f;

    int rowA[4], rowB[4];
    #pragma unroll
    for (int mi = 0; mi < 4; mi++) rowA[mi] = wm * 64 + mi * 16 + (lane & 15);
    #pragma unroll
    for (int nj = 0; nj < 4; nj++) rowB[nj] = wn * 32 + nj * 8 + (lane & 7);
    int hiA = lane >> 4;
    int hiB = (lane >> 3) & 1;

    int nk = K3 >> 6;
    prefetch(0, 0);
    prefetch(64, 1);

    for (int t = 0; t < nk; t++) {
        asm volatile("cp.async.wait_group 1;" ::: "memory");
        __syncthreads();
        if (t + 2 < nk) prefetch((t + 2) * 64, (t + 2) % 3);
        else asm volatile("cp.async.commit_group;" ::: "memory");
        int cur = t % 3;
        #pragma unroll
        for (int ks = 0; ks < 4; ks++) {
            uint32_t bf[4][2];
            #pragma unroll
            for (int nj = 0; nj < 4; nj++) {
                uint32_t off = (uint32_t)(rowB[nj] * 128 + (((2 * ks + hiB) ^ (rowB[nj] & 7)) * 16));
                ldsm2(bf[nj], sb + SBo[cur] + off);
            }
            #pragma unroll
            for (int mi = 0; mi < 4; mi++) {
                uint32_t af[4];
                uint32_t off = (uint32_t)(rowA[mi] * 128 + (((2 * ks + hiA) ^ (rowA[mi] & 7)) * 16));
                ldsm4(af, sb + SAo[cur] + off);
                #pragma unroll
                for (int nj = 0; nj < 4; nj++)
                    mma16816(acc[mi][nj], af, bf[nj]);
            }
        }
    }
    __syncthreads();

    int rbase = m0 + wm * 64 + (lane >> 2);
    int cbase = n0 + wn * 32 + 2 * (lane & 3);
    #pragma unroll
    for (int mi = 0; mi < 4; mi++) {
        #pragma unroll
        for (int rh = 0; rh < 2; rh++) {
            int row = rbase + mi * 16 + rh * 8;
            float* crow = C + (size_t)row * sC;
            #pragma unroll
            for (int nj = 0; nj < 4; nj++) {
                #pragma unroll
                for (int cl = 0; cl < 2; cl++) {
                    int col = cbase + nj * 8 + cl;
                    if (col < N) {
                        float v = acc[mi][nj][rh * 2 + cl];
                        if (bias) v += bias[col];
                        if (act == 1) v = fmaxf(v, 0.f) + log1pf(__expf(-fabsf(v)));
                        crow[col] = v;
                    }
                }
            }
        }
    }
}

// ---------------- weights: fp32 -> [Bh|Bl|Bh] (segment width Kp) ----------------
__global__ void cvt_w3(const float* __restrict__ W, int N, int K, int Np, int Kp,
                       __nv_bfloat16* __restrict__ dst) {
    int idx = blockIdx.x * blockDim.x + threadIdx.x;
    if (idx >= Np * Kp) return;
    int k = idx % Kp, n = idx / Kp;
    float v = (n < N && k < K) ? W[(size_t)n * K + k] : 0.f;
    __nv_bfloat16 h, l;
    split_bf16(v, h, l);
    size_t base = (size_t)n * (3 * Kp);
    dst[base + k] = h;
    dst[base + Kp + k] = l;
    dst[base + 2 * Kp + k] = h;
}

// ---------------- dt weights: fp32 [DI,25] -> tight [Bh(25)|Bl(25)|Bh(25)|0(53)] ----------------
__global__ void cvt_wdt(const float* __restrict__ W, __nv_bfloat16* __restrict__ dst) {
    int idx = blockIdx.x * blockDim.x + threadIdx.x;
    if (idx >= NP_DT * K3_DT) return;
    int j = idx % K3_DT, n = idx / K3_DT;
    __nv_bfloat16 o = __float2bfloat16(0.f);
    if (n < DI && j < 3 * DR) {
        int k = j % DR;
        float v = W[(size_t)n * DR + k];
        __nv_bfloat16 h, l;
        split_bf16(v, h, l);
        o = (j >= DR && j < 2 * DR) ? l : h;
    }
    dst[idx] = o;
}

// ---------------- dt slice: dbl[:, :25] -> tight [Ah(25)|Ah(25)|Al(25)|0(53)] ----------------
__global__ void cvt_dt(const float* __restrict__ dbl, __nv_bfloat16* __restrict__ dst) {
    int idx = blockIdx.x * blockDim.x + threadIdx.x;
    if (idx >= TOK * K3_DT) return;
    int j = idx % K3_DT, r = idx / K3_DT;
    __nv_bfloat16 o = __float2bfloat16(0.f);
    if (j < 3 * DR) {
        int k = j % DR;
        float v = dbl[(size_t)r * XPO + k];
        __nv_bfloat16 h, l;
        split_bf16(v, h, l);
        o = (j >= 2 * DR) ? l : h;
    }
    dst[idx] = o;
}

// ---------------- layernorm fused with split, 2-wide (Kp=448 layout) ----------------
__global__ void ln_split(const float* __restrict__ x, const float* __restrict__ g,
                         const float* __restrict__ beta, __nv_bfloat16* __restrict__ a3) {
    int t = blockIdx.x;
    const float* xr = x + (size_t)t * DM;
    float s = 0.f, s2 = 0.f;
    for (int i = threadIdx.x; i < DM; i += 128) {
        float v = xr[i]; s += v; s2 += v * v;
    }
    #pragma unroll
    for (int o = 16; o; o >>= 1) {
        s  += __shfl_down_sync(0xffffffffu, s,  o);
        s2 += __shfl_down_sync(0xffffffffu, s2, o);
    }
    __shared__ float sh[2][4];
    __shared__ float mu_s, rs_s;
    int w = threadIdx.x >> 5, ln = threadIdx.x & 31;
    if (ln == 0) { sh[0][w] = s; sh[1][w] = s2; }
    __syncthreads();
    if (threadIdx.x == 0) {
        float S  = sh[0][0] + sh[0][1] + sh[0][2] + sh[0][3];
        float S2 = sh[1][0] + sh[1][1] + sh[1][2] + sh[1][3];
        float mu = S / DM;
        float var = S2 / DM - mu * mu;
        mu_s = mu;
        rs_s = rsqrtf(var + 1e-5f);
    }
    __syncthreads();
    float mu = mu_s, rs = rs_s;
    uint32_t* row = reinterpret_cast<uint32_t*>(a3 + (size_t)t * (3 * KP_IN));
    for (int p = threadIdx.x; p < KP_IN / 2; p += 128) {
        int i = p * 2;
        uint32_t ph, pl;
        if (i < DM) {
            float2 xv = *reinterpret_cast<const float2*>(xr + i);
            float2 gv = *reinterpret_cast<const float2*>(g + i);
            float2 bv = *reinterpret_cast<const float2*>(beta + i);
            float v0 = (xv.x - mu) * rs * gv.x + bv.x;
            float v1 = (xv.y - mu) * rs * gv.y + bv.y;
            __nv_bfloat16 h0, l0, h1, l1;
            split_bf16(v0, h0, l0);
            split_bf16(v1, h1, l1);
            ph = pack2(h0, h1);
            pl = pack2(l0, l1);
        } else { ph = 0u; pl = 0u; }
        row[p] = ph;
        row[KP_IN / 2 + p] = ph;
        row[KP_IN + p] = pl;
    }
}

// ---------------- conv+SiLU fused with split, 2-wide (Kp=832) ----------------
__global__ void conv_silu_split(const float* __restrict__ xz, const float* __restrict__ cw,
                                const float* __restrict__ cb, float* __restrict__ xc,
                                __nv_bfloat16* __restrict__ a3) {
    int idx = blockIdx.x * blockDim.x + threadIdx.x;
    if (idx >= TOK * (KP_XP / 2)) return;
    int p = idx % (KP_XP / 2);
    int r = idx / (KP_XP / 2);
    int d = p * 2;
    uint32_t* row = reinterpret_cast<uint32_t*>(a3 + (size_t)r * (3 * KP_XP));
    if (d >= DI) {
        row[p] = 0u; row[KP_XP / 2 + p] = 0u; row[KP_XP + p] = 0u;
        return;
    }
    int l = r % SEQ;
    int b = r / SEQ;
    const float* base = xz + (size_t)(b * SEQ) * (2 * DI) + d;
    float4 w0 = *reinterpret_cast<const float4*>(cw + d * DC);
    float4 w1 = *reinterpret_cast<const float4*>(cw + d * DC + 4);
    float2 cbv = *reinterpret_cast<const float2*>(cb + d);
    float a0 = cbv.x, a1 = cbv.y;
    const float wa0[4] = {w0.x, w0.y, w0.z, w0.w};
    const float wa1[4] = {w1.x, w1.y, w1.z, w1.w};
    #pragma unroll
    for (int j = 0; j < DC; j++) {
        int ls = l - (DC - 1) + j;
        if (ls >= 0) {
            float2 xv = *reinterpret_cast<const float2*>(base + (size_t)ls * (2 * DI));
            a0 += wa0[j] * xv.x;
            a1 += wa1[j] * xv.y;
        }
    }
    float v0 = a0 / (1.f + __expf(-a0));
    float v1 = a1 / (1.f + __expf(-a1));
    *reinterpret_cast<float2*>(xc + (size_t)r * DI + d) = make_float2(v0, v1);
    __nv_bfloat16 h0, l0, h1, l1;
    split_bf16(v0, h0, l0);
    split_bf16(v1, h1, l1);
    uint32_t ph = pack2(h0, h1), pl = pack2(l0, l1);
    row[p] = ph; row[KP_XP / 2 + p] = ph; row[KP_XP + p] = pl;
}

// ---------------- selective scan 2-wide, writes gated y as split (Kp=832) ----------------
__global__ void scan_split(const float* __restrict__ dt, const float* __restrict__ u,
                           const float* __restrict__ dbl, const float* __restrict__ xz,
                           const float* __restrict__ A_log, const float* __restrict__ Dp,
                           __nv_bfloat16* __restrict__ a3) {
    int idx = blockIdx.x * blockDim.x + threadIdx.x;
    if (idx >= BATCH * (KP_XP / 2)) return;
    int p = idx % (KP_XP / 2);
    int b = idx / (KP_XP / 2);
    int d = p * 2;
    size_t tok0 = (size_t)b * SEQ;
    if (d >= DI) {
        for (int l = 0; l < SEQ; l++) {
            uint32_t* row = reinterpret_cast<uint32_t*>(a3 + (tok0 + l) * (3 * KP_XP));
            row[p] = 0u; row[KP_XP / 2 + p] = 0u; row[KP_XP + p] = 0u;
        }
        return;
    }
    float Aa[2][DS];
    #pragma unroll
    for (int n = 0; n < DS; n++) {
        Aa[0][n] = -__expf(A_log[d * DS + n]);
        Aa[1][n] = -__expf(A_log[(d + 1) * DS + n]);
    }
    float2 Dv = *reinterpret_cast<const float2*>(Dp + d);
    float h0[DS], h1[DS];
    #pragma unroll
    for (int n = 0; n < DS; n++) { h0[n] = 0.f; h1[n] = 0.f; }
    for (int l = 0; l < SEQ; l++) {
        size_t t = tok0 + l;
        float2 dtv = *reinterpret_cast<const float2*>(dt + t * DI + d);
        float2 uv  = *reinterpret_cast<const float2*>(u + t * DI + d);
        const float* rb = dbl + t * XPO;
        float dtu0 = dtv.x * uv.x, dtu1 = dtv.y * uv.y;
        float y0 = 0.f, y1 = 0.f;
        #pragma unroll
        for (int n = 0; n < DS; n++) {
            float Bn = rb[DR + n], Cn = rb[DR + DS + n];
            float e0 = __expf(dtv.x * Aa[0][n]);
            float e1 = __expf(dtv.y * Aa[1][n]);
            h0[n] = e0 * h0[n] + dtu0 * Bn;
            h1[n] = e1 * h1[n] + dtu1 * Bn;
            y0 += h0[n] * Cn;
            y1 += h1[n] * Cn;
        }
        float2 zv = *reinterpret_cast<const float2*>(xz + t * (2 * DI) + DI + d);
        y0 += uv.x * Dv.x;
        y1 += uv.y * Dv.y;
        float v0 = y0 * (zv.x / (1.f + __expf(-zv.x)));
        float v1 = y1 * (zv.y / (1.f + __expf(-zv.y)));
        __nv_bfloat16 hh0, ll0, hh1, ll1;
        split_bf16(v0, hh0, ll0);
        split_bf16(v1, hh1, ll1);
        uint32_t ph = pack2(hh0, hh1), pl = pack2(ll0, ll1);
        uint32_t* row = reinterpret_cast<uint32_t*>(a3 + t * (3 * KP_XP));
        row[p] = ph; row[KP_XP / 2 + p] = ph; row[KP_XP + p] = pl;
    }
}

// ---------------- classifier ----------------
__global__ void cls_kernel(const float* __restrict__ x, const float* __restrict__ w,
                           const float* __restrict__ bias, float* __restrict__ out) {
    int b = blockIdx.x;
    const float* xr = x + (size_t)b * FLAT;
    float a0 = 0.f, a1 = 0.f, a2 = 0.f;
    for (int i = threadIdx.x; i < FLAT; i += 256) {
        float v = xr[i];
        a0 += v * w[i];
        a1 += v * w[FLAT + i];
        a2 += v * w[2 * FLAT + i];
    }
    #pragma unroll
    for (int o = 16; o; o >>= 1) {
        a0 += __shfl_down_sync(0xffffffffu, a0, o);
        a1 += __shfl_down_sync(0xffffffffu, a1, o);
        a2 += __shfl_down_sync(0xffffffffu, a2, o);
    }
    __shared__ float sh[3][8];
    int wi = threadIdx.x >> 5, ln = threadIdx.x & 31;
    if (ln == 0) { sh[0][wi] = a0; sh[1][wi] = a1; sh[2][wi] = a2; }
    __syncthreads();
    if (threadIdx.x == 0) {
        float l0 = bias[0], l1 = bias[1], l2 = bias[2];
        for (int k = 0; k < 8; k++) { l0 += sh[0][k]; l1 += sh[1][k]; l2 += sh[2][k]; }
        float m = fmaxf(l0, fmaxf(l1, l2));
        float e0 = expf(l0 - m), e1 = expf(l1 - m), e2 = expf(l2 - m);
        float inv = 1.f / (e0 + e1 + e2);
        out[b * 3 + 0] = e0 * inv;
        out[b * 3 + 1] = e1 * inv;
        out[b * 3 + 2] = e2 * inv;
    }
}

// ---------------- host launch ----------------
#define MMA_SMEM 98304

extern "C" void kernel_launch(void* const* d_in, const int* in_sizes, int n_in,
                              void* d_out, int out_size) {
    const float* x_in   = (const float*)d_in[0];
    const float* ln_g   = (const float*)d_in[1];
    const float* ln_b   = (const float*)d_in[2];
    const float* inp_w  = (const float*)d_in[3];
    const float* conv_w = (const float*)d_in[4];
    const float* conv_b = (const float*)d_in[5];
    const float* xp_w   = (const float*)d_in[6];
    const float* dt_w   = (const float*)d_in[7];
    const float* dt_b   = (const float*)d_in[8];
    const float* A_log  = (const float*)d_in[9];
    const float* Dp     = (const float*)d_in[10];
    const float* out_w  = (const float*)d_in[11];
    const float* cls_w  = (const float*)d_in[12];
    const float* cls_b  = (const float*)d_in[13];
    float* out = (float*)d_out;

    float *p_xz, *p_xc, *p_dbl, *p_dt, *p_x;
    __nv_bfloat16 *p_a3, *p_adt, *p_b3;
    cudaGetSymbolAddress((void**)&p_xz,  g_xz);
    cudaGetSymbolAddress((void**)&p_xc,  g_xc);
    cudaGetSymbolAddress((void**)&p_dbl, g_dbl);
    cudaGetSymbolAddress((void**)&p_dt,  g_dt);
    cudaGetSymbolAddress((void**)&p_x,   g_x);
    cudaGetSymbolAddress((void**)&p_a3,  g_a3);
    cudaGetSymbolAddress((void**)&p_adt, g_adt);
    cudaGetSymbolAddress((void**)&p_b3,  g_b3);

    cudaFuncSetAttribute(mma_gemm, cudaFuncAttributeMaxDynamicSharedMemorySize, MMA_SMEM);

    const int MB = TOK / 128;  // 290

    for (int i = 0; i < NB; i++) {
        const float* src = (i == 0) ? x_in : p_x;
        ln_split<<<TOK, 128>>>(src, ln_g + i * DM, ln_b + i * DM, p_a3);

        // ---- in_proj
        cvt_w3<<<(NP_IN * KP_IN + 255) / 256, 256>>>(inp_w + (size_t)i * 2 * DI * DM,
                                                     2 * DI, DM, NP_IN, KP_IN, p_b3);
        mma_gemm<<<dim3(MB, NP_IN / 128), 256, MMA_SMEM>>>(p_a3, p_b3, 3 * KP_IN,
                                                           p_xz, 2 * DI, 2 * DI, nullptr, 0);

        // conv + SiLU + split (2-wide)
        conv_silu_split<<<(TOK * (KP_XP / 2) + 255) / 256, 256>>>(
            p_xz, conv_w + (size_t)i * DI * DC, conv_b + (size_t)i * DI, p_xc, p_a3);

        // ---- x_proj
        cvt_w3<<<(NP_XP * KP_XP + 255) / 256, 256>>>(xp_w + (size_t)i * XPO * DI,
                                                     XPO, DI, NP_XP, KP_XP, p_b3);
        mma_gemm<<<dim3(MB, NP_XP / 128), 256, MMA_SMEM>>>(p_a3, p_b3, 3 * KP_XP,
                                                           p_dbl, XPO, XPO, nullptr, 0);

        // ---- dt_proj (tight K3=128)
        cvt_dt<<<(TOK * K3_DT + 255) / 256, 256>>>(p_dbl, p_adt);
        cvt_wdt<<<(NP_DT * K3_DT + 255) / 256, 256>>>(dt_w + (size_t)i * DI * DR, p_b3);
        mma_gemm<<<dim3(MB, NP_DT / 128), 256, MMA_SMEM>>>(p_adt, p_b3, K3_DT,
                                                           p_dt, DI, DI, dt_b + (size_t)i * DI, 1);

        // scan + gate + split (2-wide)
        scan_split<<<(BATCH * (KP_XP / 2) + 127) / 128, 128>>>(
            p_dt, p_xc, p_dbl, p_xz,
            A_log + (size_t)i * DI * DS, Dp + (size_t)i * DI, p_a3);

        // ---- out_proj
        cvt_w3<<<(NP_OUT * KP_OUT + 255) / 256, 256>>>(out_w + (size_t)i * DM * DI,
                                                       DM, DI, NP_OUT, KP_OUT, p_b3);
        mma_gemm<<<dim3(MB, NP_OUT / 128), 256, MMA_SMEM>>>(p_a3, p_b3, 3 * KP_OUT,
                                                            p_x, DM, DM, nullptr, 0);
    }

    cls_kernel<<<BATCH, 256>>>(p_x, cls_w, cls_b, out);
}

// round 16
// speedup vs baseline: 1.4124x; 1.4124x over previous
#include <cuda_runtime.h>
#include <cuda_bf16.h>
#include <cstdint>
#include <cstddef>

#define BATCH 256
#define SEQ 145
#define DM 388
#define DI 776
#define DS 16
#define DC 4
#define DR 25
#define NB 5
#define TOK (BATCH*SEQ)          /* 37120 */
#define XPO (DR + 2*DS)          /* 57 */
#define FLAT (SEQ*DM)            /* 56260 */

// padded K (before 3x split concat) and padded N per GEMM
#define KP_IN  448
#define NP_IN  1664
#define KP_XP  832
#define NP_XP  128
#define K3_DT  128               /* tight: [Ah(25)|Ah(25)|Al(25)|0(53)] */
#define NP_DT  896
#define KP_OUT 832
#define NP_OUT 512
#define MAXK3  (3*832)           /* 2496 */

// ---------------- scratch ----------------
__device__ float g_xz [TOK*2*DI];
__device__ float g_xc [TOK*DI];
__device__ float g_dbl[TOK*XPO];
__device__ float g_dt [TOK*DI];
__device__ float g_x  [TOK*DM];
__device__ __nv_bfloat16 g_a3[(size_t)TOK*MAXK3];       // split activations [TOK, 3*Kp]
__device__ __nv_bfloat16 g_adt[(size_t)TOK*K3_DT];      // dt split
__device__ __nv_bfloat16 g_b3[(size_t)NP_IN*3*KP_IN];   // split weights (max 1664*1344)

// ---------------- helpers ----------------
__device__ __forceinline__ uint32_t smem_u32(const void* p) {
    uint32_t a;
    asm("{ .reg .u64 t; cvta.to.shared.u64 t, %1; cvt.u32.u64 %0, t; }" : "=r"(a) : "l"(p));
    return a;
}
__device__ __forceinline__ void cpasync16(uint32_t s, const void* g) {
    asm volatile("cp.async.cg.shared.global [%0], [%1], 16;" :: "r"(s), "l"(g));
}
__device__ __forceinline__ void ldsm4(uint32_t* r, uint32_t a) {
    asm volatile("ldmatrix.sync.aligned.m8n8.x4.shared.b16 {%0,%1,%2,%3}, [%4];"
                 : "=r"(r[0]), "=r"(r[1]), "=r"(r[2]), "=r"(r[3]) : "r"(a));
}
__device__ __forceinline__ void ldsm2(uint32_t* r, uint32_t a) {
    asm volatile("ldmatrix.sync.aligned.m8n8.x2.shared.b16 {%0,%1}, [%2];"
                 : "=r"(r[0]), "=r"(r[1]) : "r"(a));
}
__device__ __forceinline__ void mma16816(float* d, const uint32_t* a, const uint32_t* b) {
    asm volatile("mma.sync.aligned.m16n8k16.row.col.f32.bf16.bf16.f32 "
                 "{%0,%1,%2,%3}, {%4,%5,%6,%7}, {%8,%9}, {%0,%1,%2,%3};"
                 : "+f"(d[0]), "+f"(d[1]), "+f"(d[2]), "+f"(d[3])
                 : "r"(a[0]), "r"(a[1]), "r"(a[2]), "r"(a[3]), "r"(b[0]), "r"(b[1]));
}
__device__ __forceinline__ void split_bf16(float v, __nv_bfloat16& h, __nv_bfloat16& l) {
    h = __float2bfloat16(v);
    l = __float2bfloat16(v - __bfloat162float(h));
}
__device__ __forceinline__ uint32_t pack2(__nv_bfloat16 a, __nv_bfloat16 b) {
    __nv_bfloat162 t = __halves2bfloat162(a, b);
    return *reinterpret_cast<uint32_t*>(&t);
}

// ---------------- bf16 HMMA GEMM (3-stage cp.async pipeline, 2 CTA/SM) ----------------
// EXACT R12 mainloop (7.50 ms config). C[M,N] = A3[M,K3] x B3[Np,K3]^T, fp32 accum.
__global__ void __launch_bounds__(256, 2)
mma_gemm(const __nv_bfloat16* __restrict__ A, const __nv_bfloat16* __restrict__ B, int K3,
         float* __restrict__ C, int sC, int N,
         const float* __restrict__ bias, int act) {
    extern __shared__ char smem[];
    uint32_t sb = smem_u32(smem);
    const uint32_t SAo[3] = {0, 32768, 65536};
    const uint32_t SBo[3] = {16384, 49152, 81920};
    int tid = threadIdx.x, wid = tid >> 5, lane = tid & 31;
    int wm = wid & 1, wn = wid >> 1;          // 2 x 4 warp grid
    int m0 = blockIdx.x * 128, n0 = blockIdx.y * 128;

    int lrow[4], lc[4];
    uint32_t lso[4];
    #pragma unroll
    for (int j = 0; j < 4; j++) {
        int cid = tid + j * 256;
        lrow[j] = cid >> 3;
        lc[j] = cid & 7;
        lso[j] = (uint32_t)(lrow[j] * 128 + ((lc[j] ^ (lrow[j] & 7)) * 16));
    }

    auto prefetch = [&](int k0, int st) {
        #pragma unroll
        for (int j = 0; j < 4; j++) {
            const __nv_bfloat16* ga = A + (size_t)(m0 + lrow[j]) * K3 + k0 + lc[j] * 8;
            const __nv_bfloat16* gb = B + (size_t)(n0 + lrow[j]) * K3 + k0 + lc[j] * 8;
            cpasync16(sb + SAo[st] + lso[j], ga);
            cpasync16(sb + SBo[st] + lso[j], gb);
        }
        asm volatile("cp.async.commit_group;" ::: "memory");
    };

    float acc[4][4][4];
    #pragma unroll
    for (int i = 0; i < 4; i++)
        #pragma unroll
        for (int j = 0; j < 4; j++)
            #pragma unroll
            for (int r = 0; r < 4; r++) acc[i][j][r] = 0.f;

    int rowA[4], rowB[4];
    #pragma unroll
    for (int mi = 0; mi < 4; mi++) rowA[mi] = wm * 64 + mi * 16 + (lane & 15);
    #pragma unroll
    for (int nj = 0; nj < 4; nj++) rowB[nj] = wn * 32 + nj * 8 + (lane & 7);
    int hiA = lane >> 4;
    int hiB = (lane >> 3) & 1;

    int nk = K3 >> 6;
    prefetch(0, 0);
    prefetch(64, 1);

    for (int t = 0; t < nk; t++) {
        asm volatile("cp.async.wait_group 1;" ::: "memory");
        __syncthreads();
        if (t + 2 < nk) prefetch((t + 2) * 64, (t + 2) % 3);
        else asm volatile("cp.async.commit_group;" ::: "memory");
        int cur = t % 3;
        #pragma unroll
        for (int ks = 0; ks < 4; ks++) {
            uint32_t bf[4][2];
            #pragma unroll
            for (int nj = 0; nj < 4; nj++) {
                uint32_t off = (uint32_t)(rowB[nj] * 128 + (((2 * ks + hiB) ^ (rowB[nj] & 7)) * 16));
                ldsm2(bf[nj], sb + SBo[cur] + off);
            }
            #pragma unroll
            for (int mi = 0; mi < 4; mi++) {
                uint32_t af[4];
                uint32_t off = (uint32_t)(rowA[mi] * 128 + (((2 * ks + hiA) ^ (rowA[mi] & 7)) * 16));
                ldsm4(af, sb + SAo[cur] + off);
                #pragma unroll
                for (int nj = 0; nj < 4; nj++)
                    mma16816(acc[mi][nj], af, bf[nj]);
            }
        }
    }
    __syncthreads();

    int rbase = m0 + wm * 64 + (lane >> 2);
    int cbase = n0 + wn * 32 + 2 * (lane & 3);
    #pragma unroll
    for (int mi = 0; mi < 4; mi++) {
        #pragma unroll
        for (int rh = 0; rh < 2; rh++) {
            int row = rbase + mi * 16 + rh * 8;
            float* crow = C + (size_t)row * sC;
            #pragma unroll
            for (int nj = 0; nj < 4; nj++) {
                #pragma unroll
                for (int cl = 0; cl < 2; cl++) {
                    int col = cbase + nj * 8 + cl;
                    if (col < N) {
                        float v = acc[mi][nj][rh * 2 + cl];
                        if (bias) v += bias[col];
                        if (act == 1) v = fmaxf(v, 0.f) + log1pf(__expf(-fabsf(v)));
                        crow[col] = v;
                    }
                }
            }
        }
    }
}

// ---------------- weights: fp32 -> [Bh|Bl|Bh] (segment width Kp) ----------------
__global__ void cvt_w3(const float* __restrict__ W, int N, int K, int Np, int Kp,
                       __nv_bfloat16* __restrict__ dst) {
    int idx = blockIdx.x * blockDim.x + threadIdx.x;
    if (idx >= Np * Kp) return;
    int k = idx % Kp, n = idx / Kp;
    float v = (n < N && k < K) ? W[(size_t)n * K + k] : 0.f;
    __nv_bfloat16 h, l;
    split_bf16(v, h, l);
    size_t base = (size_t)n * (3 * Kp);
    dst[base + k] = h;
    dst[base + Kp + k] = l;
    dst[base + 2 * Kp + k] = h;
}

// ---------------- dt weights: fp32 [DI,25] -> tight [Bh(25)|Bl(25)|Bh(25)|0(53)] ----------------
__global__ void cvt_wdt(const float* __restrict__ W, __nv_bfloat16* __restrict__ dst) {
    int idx = blockIdx.x * blockDim.x + threadIdx.x;
    if (idx >= NP_DT * K3_DT) return;
    int j = idx % K3_DT, n = idx / K3_DT;
    __nv_bfloat16 o = __float2bfloat16(0.f);
    if (n < DI && j < 3 * DR) {
        int k = j % DR;
        float v = W[(size_t)n * DR + k];
        __nv_bfloat16 h, l;
        split_bf16(v, h, l);
        o = (j >= DR && j < 2 * DR) ? l : h;
    }
    dst[idx] = o;
}

// ---------------- dt slice: dbl[:, :25] -> tight [Ah(25)|Ah(25)|Al(25)|0(53)] ----------------
__global__ void cvt_dt(const float* __restrict__ dbl, __nv_bfloat16* __restrict__ dst) {
    int idx = blockIdx.x * blockDim.x + threadIdx.x;
    if (idx >= TOK * K3_DT) return;
    int j = idx % K3_DT, r = idx / K3_DT;
    __nv_bfloat16 o = __float2bfloat16(0.f);
    if (j < 3 * DR) {
        int k = j % DR;
        float v = dbl[(size_t)r * XPO + k];
        __nv_bfloat16 h, l;
        split_bf16(v, h, l);
        o = (j >= 2 * DR) ? l : h;
    }
    dst[idx] = o;
}

// ---------------- layernorm fused with split, 2-wide (Kp=448 layout) ----------------
__global__ void ln_split(const float* __restrict__ x, const float* __restrict__ g,
                         const float* __restrict__ beta, __nv_bfloat16* __restrict__ a3) {
    int t = blockIdx.x;
    const float* xr = x + (size_t)t * DM;
    float s = 0.f, s2 = 0.f;
    for (int i = threadIdx.x; i < DM; i += 128) {
        float v = xr[i]; s += v; s2 += v * v;
    }
    #pragma unroll
    for (int o = 16; o; o >>= 1) {
        s  += __shfl_down_sync(0xffffffffu, s,  o);
        s2 += __shfl_down_sync(0xffffffffu, s2, o);
    }
    __shared__ float sh[2][4];
    __shared__ float mu_s, rs_s;
    int w = threadIdx.x >> 5, ln = threadIdx.x & 31;
    if (ln == 0) { sh[0][w] = s; sh[1][w] = s2; }
    __syncthreads();
    if (threadIdx.x == 0) {
        float S  = sh[0][0] + sh[0][1] + sh[0][2] + sh[0][3];
        float S2 = sh[1][0] + sh[1][1] + sh[1][2] + sh[1][3];
        float mu = S / DM;
        float var = S2 / DM - mu * mu;
        mu_s = mu;
        rs_s = rsqrtf(var + 1e-5f);
    }
    __syncthreads();
    float mu = mu_s, rs = rs_s;
    uint32_t* row = reinterpret_cast<uint32_t*>(a3 + (size_t)t * (3 * KP_IN));
    for (int p = threadIdx.x; p < KP_IN / 2; p += 128) {
        int i = p * 2;
        uint32_t ph, pl;
        if (i < DM) {
            float2 xv = *reinterpret_cast<const float2*>(xr + i);
            float2 gv = *reinterpret_cast<const float2*>(g + i);
            float2 bv = *reinterpret_cast<const float2*>(beta + i);
            float v0 = (xv.x - mu) * rs * gv.x + bv.x;
            float v1 = (xv.y - mu) * rs * gv.y + bv.y;
            __nv_bfloat16 h0, l0, h1, l1;
            split_bf16(v0, h0, l0);
            split_bf16(v1, h1, l1);
            ph = pack2(h0, h1);
            pl = pack2(l0, l1);
        } else { ph = 0u; pl = 0u; }
        row[p] = ph;
        row[KP_IN / 2 + p] = ph;
        row[KP_IN + p] = pl;
    }
}

// ---------------- conv+SiLU fused with split, 2-wide (Kp=832) ----------------
__global__ void conv_silu_split(const float* __restrict__ xz, const float* __restrict__ cw,
                                const float* __restrict__ cb, float* __restrict__ xc,
                                __nv_bfloat16* __restrict__ a3) {
    int idx = blockIdx.x * blockDim.x + threadIdx.x;
    if (idx >= TOK * (KP_XP / 2)) return;
    int p = idx % (KP_XP / 2);
    int r = idx / (KP_XP / 2);
    int d = p * 2;
    uint32_t* row = reinterpret_cast<uint32_t*>(a3 + (size_t)r * (3 * KP_XP));
    if (d >= DI) {
        row[p] = 0u; row[KP_XP / 2 + p] = 0u; row[KP_XP + p] = 0u;
        return;
    }
    int l = r % SEQ;
    int b = r / SEQ;
    const float* base = xz + (size_t)(b * SEQ) * (2 * DI) + d;
    float4 w0 = *reinterpret_cast<const float4*>(cw + d * DC);
    float4 w1 = *reinterpret_cast<const float4*>(cw + d * DC + 4);
    float2 cbv = *reinterpret_cast<const float2*>(cb + d);
    float a0 = cbv.x, a1 = cbv.y;
    const float wa0[4] = {w0.x, w0.y, w0.z, w0.w};
    const float wa1[4] = {w1.x, w1.y, w1.z, w1.w};
    #pragma unroll
    for (int j = 0; j < DC; j++) {
        int ls = l - (DC - 1) + j;
        if (ls >= 0) {
            float2 xv = *reinterpret_cast<const float2*>(base + (size_t)ls * (2 * DI));
            a0 += wa0[j] * xv.x;
            a1 += wa1[j] * xv.y;
        }
    }
    float v0 = a0 / (1.f + __expf(-a0));
    float v1 = a1 / (1.f + __expf(-a1));
    *reinterpret_cast<float2*>(xc + (size_t)r * DI + d) = make_float2(v0, v1);
    __nv_bfloat16 h0, l0, h1, l1;
    split_bf16(v0, h0, l0);
    split_bf16(v1, h1, l1);
    uint32_t ph = pack2(h0, h1), pl = pack2(l0, l1);
    row[p] = ph; row[KP_XP / 2 + p] = ph; row[KP_XP + p] = pl;
}

// ---------------- selective scan 2-wide, writes gated y as split (Kp=832) ----------------
__global__ void scan_split(const float* __restrict__ dt, const float* __restrict__ u,
                           const float* __restrict__ dbl, const float* __restrict__ xz,
                           const float* __restrict__ A_log, const float* __restrict__ Dp,
                           __nv_bfloat16* __restrict__ a3) {
    int idx = blockIdx.x * blockDim.x + threadIdx.x;
    if (idx >= BATCH * (KP_XP / 2)) return;
    int p = idx % (KP_XP / 2);
    int b = idx / (KP_XP / 2);
    int d = p * 2;
    size_t tok0 = (size_t)b * SEQ;
    if (d >= DI) {
        for (int l = 0; l < SEQ; l++) {
            uint32_t* row = reinterpret_cast<uint32_t*>(a3 + (tok0 + l) * (3 * KP_XP));
            row[p] = 0u; row[KP_XP / 2 + p] = 0u; row[KP_XP + p] = 0u;
        }
        return;
    }
    float Aa[2][DS];
    #pragma unroll
    for (int n = 0; n < DS; n++) {
        Aa[0][n] = -__expf(A_log[d * DS + n]);
        Aa[1][n] = -__expf(A_log[(d + 1) * DS + n]);
    }
    float2 Dv = *reinterpret_cast<const float2*>(Dp + d);
    float h0[DS], h1[DS];
    #pragma unroll
    for (int n = 0; n < DS; n++) { h0[n] = 0.f; h1[n] = 0.f; }
    for (int l = 0; l < SEQ; l++) {
        size_t t = tok0 + l;
        float2 dtv = *reinterpret_cast<const float2*>(dt + t * DI + d);
        float2 uv  = *reinterpret_cast<const float2*>(u + t * DI + d);
        const float* rb = dbl + t * XPO;
        float dtu0 = dtv.x * uv.x, dtu1 = dtv.y * uv.y;
        float y0 = 0.f, y1 = 0.f;
        #pragma unroll
        for (int n = 0; n < DS; n++) {
            float Bn = rb[DR + n], Cn = rb[DR + DS + n];
            float e0 = __expf(dtv.x * Aa[0][n]);
            float e1 = __expf(dtv.y * Aa[1][n]);
            h0[n] = e0 * h0[n] + dtu0 * Bn;
            h1[n] = e1 * h1[n] + dtu1 * Bn;
            y0 += h0[n] * Cn;
            y1 += h1[n] * Cn;
        }
        float2 zv = *reinterpret_cast<const float2*>(xz + t * (2 * DI) + DI + d);
        y0 += uv.x * Dv.x;
        y1 += uv.y * Dv.y;
        float v0 = y0 * (zv.x / (1.f + __expf(-zv.x)));
        float v1 = y1 * (zv.y / (1.f + __expf(-zv.y)));
        __nv_bfloat16 hh0, ll0, hh1, ll1;
        split_bf16(v0, hh0, ll0);
        split_bf16(v1, hh1, ll1);
        uint32_t ph = pack2(hh0, hh1), pl = pack2(ll0, ll1);
        uint32_t* row = reinterpret_cast<uint32_t*>(a3 + t * (3 * KP_XP));
        row[p] = ph; row[KP_XP / 2 + p] = ph; row[KP_XP + p] = pl;
    }
}

// ---------------- classifier ----------------
__global__ void cls_kernel(const float* __restrict__ x, const float* __restrict__ w,
                           const float* __restrict__ bias, float* __restrict__ out) {
    int b = blockIdx.x;
    const float* xr = x + (size_t)b * FLAT;
    float a0 = 0.f, a1 = 0.f, a2 = 0.f;
    for (int i = threadIdx.x; i < FLAT; i += 256) {
        float v = xr[i];
        a0 += v * w[i];
        a1 += v * w[FLAT + i];
        a2 += v * w[2 * FLAT + i];
    }
    #pragma unroll
    for (int o = 16; o; o >>= 1) {
        a0 += __shfl_down_sync(0xffffffffu, a0, o);
        a1 += __shfl_down_sync(0xffffffffu, a1, o);
        a2 += __shfl_down_sync(0xffffffffu, a2, o);
    }
    __shared__ float sh[3][8];
    int wi = threadIdx.x >> 5, ln = threadIdx.x & 31;
    if (ln == 0) { sh[0][wi] = a0; sh[1][wi] = a1; sh[2][wi] = a2; }
    __syncthreads();
    if (threadIdx.x == 0) {
        float l0 = bias[0], l1 = bias[1], l2 = bias[2];
        for (int k = 0; k < 8; k++) { l0 += sh[0][k]; l1 += sh[1][k]; l2 += sh[2][k]; }
        float m = fmaxf(l0, fmaxf(l1, l2));
        float e0 = expf(l0 - m), e1 = expf(l1 - m), e2 = expf(l2 - m);
        float inv = 1.f / (e0 + e1 + e2);
        out[b * 3 + 0] = e0 * inv;
        out[b * 3 + 1] = e1 * inv;
        out[b * 3 + 2] = e2 * inv;
    }
}

// ---------------- host launch ----------------
#define MMA_SMEM 98304

extern "C" void kernel_launch(void* const* d_in, const int* in_sizes, int n_in,
                              void* d_out, int out_size) {
    const float* x_in   = (const float*)d_in[0];
    const float* ln_g   = (const float*)d_in[1];
    const float* ln_b   = (const float*)d_in[2];
    const float* inp_w  = (const float*)d_in[3];
    const float* conv_w = (const float*)d_in[4];
    const float* conv_b = (const float*)d_in[5];
    const float* xp_w   = (const float*)d_in[6];
    const float* dt_w   = (const float*)d_in[7];
    const float* dt_b   = (const float*)d_in[8];
    const float* A_log  = (const float*)d_in[9];
    const float* Dp     = (const float*)d_in[10];
    const float* out_w  = (const float*)d_in[11];
    const float* cls_w  = (const float*)d_in[12];
    const float* cls_b  = (const float*)d_in[13];
    float* out = (float*)d_out;

    float *p_xz, *p_xc, *p_dbl, *p_dt, *p_x;
    __nv_bfloat16 *p_a3, *p_adt, *p_b3;
    cudaGetSymbolAddress((void**)&p_xz,  g_xz);
    cudaGetSymbolAddress((void**)&p_xc,  g_xc);
    cudaGetSymbolAddress((void**)&p_dbl, g_dbl);
    cudaGetSymbolAddress((void**)&p_dt,  g_dt);
    cudaGetSymbolAddress((void**)&p_x,   g_x);
    cudaGetSymbolAddress((void**)&p_a3,  g_a3);
    cudaGetSymbolAddress((void**)&p_adt, g_adt);
    cudaGetSymbolAddress((void**)&p_b3,  g_b3);

    cudaFuncSetAttribute(mma_gemm, cudaFuncAttributeMaxDynamicSharedMemorySize, MMA_SMEM);

    const int MB = TOK / 128;  // 290

    for (int i = 0; i < NB; i++) {
        const float* src = (i == 0) ? x_in : p_x;
        ln_split<<<TOK, 128>>>(src, ln_g + i * DM, ln_b + i * DM, p_a3);

        // ---- in_proj
        cvt_w3<<<(NP_IN * KP_IN + 255) / 256, 256>>>(inp_w + (size_t)i * 2 * DI * DM,
                                                     2 * DI, DM, NP_IN, KP_IN, p_b3);
        mma_gemm<<<dim3(MB, NP_IN / 128), 256, MMA_SMEM>>>(p_a3, p_b3, 3 * KP_IN,
                                                           p_xz, 2 * DI, 2 * DI, nullptr, 0);

        // conv + SiLU + split (2-wide)
        conv_silu_split<<<(TOK * (KP_XP / 2) + 255) / 256, 256>>>(
            p_xz, conv_w + (size_t)i * DI * DC, conv_b + (size_t)i * DI, p_xc, p_a3);

        // ---- x_proj
        cvt_w3<<<(NP_XP * KP_XP + 255) / 256, 256>>>(xp_w + (size_t)i * XPO * DI,
                                                     XPO, DI, NP_XP, KP_XP, p_b3);
        mma_gemm<<<dim3(MB, NP_XP / 128), 256, MMA_SMEM>>>(p_a3, p_b3, 3 * KP_XP,
                                                           p_dbl, XPO, XPO, nullptr, 0);

        // ---- dt_proj (tight K3=128)
        cvt_dt<<<(TOK * K3_DT + 255) / 256, 256>>>(p_dbl, p_adt);
        cvt_wdt<<<(NP_DT * K3_DT + 255) / 256, 256>>>(dt_w + (size_t)i * DI * DR, p_b3);
        mma_gemm<<<dim3(MB, NP_DT / 128), 256, MMA_SMEM>>>(p_adt, p_b3, K3_DT,
                                                           p_dt, DI, DI, dt_b + (size_t)i * DI, 1);

        // scan + gate + split (2-wide)
        scan_split<<<(BATCH * (KP_XP / 2) + 127) / 128, 128>>>(
            p_dt, p_xc, p_dbl, p_xz,
            A_log + (size_t)i * DI * DS, Dp + (size_t)i * DI, p_a3);

        // ---- out_proj
        cvt_w3<<<(NP_OUT * KP_OUT + 255) / 256, 256>>>(out_w + (size_t)i * DM * DI,
                                                       DM, DI, NP_OUT, KP_OUT, p_b3);
        mma_gemm<<<dim3(MB, NP_OUT / 128), 256, MMA_SMEM>>>(p_a3, p_b3, 3 * KP_OUT,
                                                            p_x, DM, DM, nullptr, 0);
    }

    cls_kernel<<<BATCH, 256>>>(p_x, cls_w, cls_b, out);
}

// round 17
// speedup vs baseline: 1.4314x; 1.0135x over previous
#include <cuda_runtime.h>
#include <cuda_bf16.h>
#include <cstdint>
#include <cstddef>

#define BATCH 256
#define SEQ 145
#define DM 388
#define DI 776
#define DS 16
#define DC 4
#define DR 25
#define NB 5
#define TOK (BATCH*SEQ)          /* 37120 */
#define XPO (DR + 2*DS)          /* 57 */
#define FLAT (SEQ*DM)            /* 56260 */

// padded K (before 3x split concat) and padded N per GEMM
#define KP_IN  448
#define NP_IN  1664
#define KP_XP  832
#define NP_XP  128
#define K3_DT  128               /* tight: [Ah(25)|Ah(25)|Al(25)|0(53)] */
#define NP_DT  896
#define KP_OUT 832
#define NP_OUT 512
#define MAXK3  (3*832)           /* 2496 */

// ---------------- scratch ----------------
__device__ float g_xz [TOK*2*DI];
__device__ float g_xc [TOK*DI];
__device__ float g_dbl[TOK*XPO];
__device__ float g_dt [TOK*DI];
__device__ float g_x  [TOK*DM];
__device__ __nv_bfloat16 g_a3[(size_t)TOK*MAXK3];       // split activations [TOK, 3*Kp]
__device__ __nv_bfloat16 g_adt[(size_t)TOK*K3_DT];      // dt split
__device__ __nv_bfloat16 g_b3[(size_t)NP_IN*3*KP_IN];   // split weights (max 1664*1344)

// ---------------- helpers ----------------
__device__ __forceinline__ uint32_t smem_u32(const void* p) {
    uint32_t a;
    asm("{ .reg .u64 t; cvta.to.shared.u64 t, %1; cvt.u32.u64 %0, t; }" : "=r"(a) : "l"(p));
    return a;
}
__device__ __forceinline__ void cpasync16(uint32_t s, const void* g) {
    asm volatile("cp.async.cg.shared.global [%0], [%1], 16;" :: "r"(s), "l"(g));
}
__device__ __forceinline__ void ldsm4(uint32_t* r, uint32_t a) {
    asm volatile("ldmatrix.sync.aligned.m8n8.x4.shared.b16 {%0,%1,%2,%3}, [%4];"
                 : "=r"(r[0]), "=r"(r[1]), "=r"(r[2]), "=r"(r[3]) : "r"(a));
}
__device__ __forceinline__ void ldsm2(uint32_t* r, uint32_t a) {
    asm volatile("ldmatrix.sync.aligned.m8n8.x2.shared.b16 {%0,%1}, [%2];"
                 : "=r"(r[0]), "=r"(r[1]) : "r"(a));
}
__device__ __forceinline__ void mma16816(float* d, const uint32_t* a, const uint32_t* b) {
    asm volatile("mma.sync.aligned.m16n8k16.row.col.f32.bf16.bf16.f32 "
                 "{%0,%1,%2,%3}, {%4,%5,%6,%7}, {%8,%9}, {%0,%1,%2,%3};"
                 : "+f"(d[0]), "+f"(d[1]), "+f"(d[2]), "+f"(d[3])
                 : "r"(a[0]), "r"(a[1]), "r"(a[2]), "r"(a[3]), "r"(b[0]), "r"(b[1]));
}
__device__ __forceinline__ void split_bf16(float v, __nv_bfloat16& h, __nv_bfloat16& l) {
    h = __float2bfloat16(v);
    l = __float2bfloat16(v - __bfloat162float(h));
}
__device__ __forceinline__ uint32_t pack2(__nv_bfloat16 a, __nv_bfloat16 b) {
    __nv_bfloat162 t = __halves2bfloat162(a, b);
    return *reinterpret_cast<uint32_t*>(&t);
}

// ---------------- bf16 HMMA GEMM (3-stage cp.async pipeline, 2 CTA/SM) ----------------
// 1-D grid with supertile rasterization: groups of GM m-tiles x NT n-tiles are
// contiguous in launch order so co-resident CTAs share A/B tiles in L2.
// C[M,N] = A3[M,K3] x B3[Np,K3]^T, fp32 accum. Mainloop identical to the 7.50 ms config.
__global__ void __launch_bounds__(256, 2)
mma_gemm(const __nv_bfloat16* __restrict__ A, const __nv_bfloat16* __restrict__ B, int K3,
         float* __restrict__ C, int sC, int N,
         const float* __restrict__ bias, int act, int MB, int NT, int GM) {
    extern __shared__ char smem[];
    uint32_t sb = smem_u32(smem);
    const uint32_t SAo[3] = {0, 32768, 65536};
    const uint32_t SBo[3] = {16384, 49152, 81920};
    int tid = threadIdx.x, wid = tid >> 5, lane = tid & 31;
    int wm = wid & 1, wn = wid >> 1;          // 2 x 4 warp grid

    // supertile decode
    int bid = blockIdx.x;
    int tpg = GM * NT;
    int grp = bid / tpg;
    int rem = bid - grp * tpg;
    int gm = MB - grp * GM; if (gm > GM) gm = GM;
    int mt = grp * GM + rem % gm;
    int nt = rem / gm;
    int m0 = mt * 128, n0 = nt * 128;

    int lrow[4], lc[4];
    uint32_t lso[4];
    #pragma unroll
    for (int j = 0; j < 4; j++) {
        int cid = tid + j * 256;
        lrow[j] = cid >> 3;
        lc[j] = cid & 7;
        lso[j] = (uint32_t)(lrow[j] * 128 + ((lc[j] ^ (lrow[j] & 7)) * 16));
    }

    auto prefetch = [&](int k0, int st) {
        #pragma unroll
        for (int j = 0; j < 4; j++) {
            const __nv_bfloat16* ga = A + (size_t)(m0 + lrow[j]) * K3 + k0 + lc[j] * 8;
            const __nv_bfloat16* gb = B + (size_t)(n0 + lrow[j]) * K3 + k0 + lc[j] * 8;
            cpasync16(sb + SAo[st] + lso[j], ga);
            cpasync16(sb + SBo[st] + lso[j], gb);
        }
        asm volatile("cp.async.commit_group;" ::: "memory");
    };

    float acc[4][4][4];
    #pragma unroll
    for (int i = 0; i < 4; i++)
        #pragma unroll
        for (int j = 0; j < 4; j++)
            #pragma unroll
            for (int r = 0; r < 4; r++) acc[i][j][r] = 0.f;

    int rowA[4], rowB[4];
    #pragma unroll
    for (int mi = 0; mi < 4; mi++) rowA[mi] = wm * 64 + mi * 16 + (lane & 15);
    #pragma unroll
    for (int nj = 0; nj < 4; nj++) rowB[nj] = wn * 32 + nj * 8 + (lane & 7);
    int hiA = lane >> 4;
    int hiB = (lane >> 3) & 1;

    int nk = K3 >> 6;
    prefetch(0, 0);
    prefetch(64, 1);

    for (int t = 0; t < nk; t++) {
        asm volatile("cp.async.wait_group 1;" ::: "memory");
        __syncthreads();
        if (t + 2 < nk) prefetch((t + 2) * 64, (t + 2) % 3);
        else asm volatile("cp.async.commit_group;" ::: "memory");
        int cur = t % 3;
        #pragma unroll
        for (int ks = 0; ks < 4; ks++) {
            uint32_t bf[4][2];
            #pragma unroll
            for (int nj = 0; nj < 4; nj++) {
                uint32_t off = (uint32_t)(rowB[nj] * 128 + (((2 * ks + hiB) ^ (rowB[nj] & 7)) * 16));
                ldsm2(bf[nj], sb + SBo[cur] + off);
            }
            #pragma unroll
            for (int mi = 0; mi < 4; mi++) {
                uint32_t af[4];
                uint32_t off = (uint32_t)(rowA[mi] * 128 + (((2 * ks + hiA) ^ (rowA[mi] & 7)) * 16));
                ldsm4(af, sb + SAo[cur] + off);
                #pragma unroll
                for (int nj = 0; nj < 4; nj++)
                    mma16816(acc[mi][nj], af, bf[nj]);
            }
        }
    }
    __syncthreads();

    int rbase = m0 + wm * 64 + (lane >> 2);
    int cbase = n0 + wn * 32 + 2 * (lane & 3);
    #pragma unroll
    for (int mi = 0; mi < 4; mi++) {
        #pragma unroll
        for (int rh = 0; rh < 2; rh++) {
            int row = rbase + mi * 16 + rh * 8;
            float* crow = C + (size_t)row * sC;
            #pragma unroll
            for (int nj = 0; nj < 4; nj++) {
                #pragma unroll
                for (int cl = 0; cl < 2; cl++) {
                    int col = cbase + nj * 8 + cl;
                    if (col < N) {
                        float v = acc[mi][nj][rh * 2 + cl];
                        if (bias) v += bias[col];
                        if (act == 1) v = fmaxf(v, 0.f) + log1pf(__expf(-fabsf(v)));
                        crow[col] = v;
                    }
                }
            }
        }
    }
}

// ---------------- weights: fp32 -> [Bh|Bl|Bh] (segment width Kp) ----------------
__global__ void cvt_w3(const float* __restrict__ W, int N, int K, int Np, int Kp,
                       __nv_bfloat16* __restrict__ dst) {
    int idx = blockIdx.x * blockDim.x + threadIdx.x;
    if (idx >= Np * Kp) return;
    int k = idx % Kp, n = idx / Kp;
    float v = (n < N && k < K) ? W[(size_t)n * K + k] : 0.f;
    __nv_bfloat16 h, l;
    split_bf16(v, h, l);
    size_t base = (size_t)n * (3 * Kp);
    dst[base + k] = h;
    dst[base + Kp + k] = l;
    dst[base + 2 * Kp + k] = h;
}

// ---------------- dt weights: fp32 [DI,25] -> tight [Bh(25)|Bl(25)|Bh(25)|0(53)] ----------------
__global__ void cvt_wdt(const float* __restrict__ W, __nv_bfloat16* __restrict__ dst) {
    int idx = blockIdx.x * blockDim.x + threadIdx.x;
    if (idx >= NP_DT * K3_DT) return;
    int j = idx % K3_DT, n = idx / K3_DT;
    __nv_bfloat16 o = __float2bfloat16(0.f);
    if (n < DI && j < 3 * DR) {
        int k = j % DR;
        float v = W[(size_t)n * DR + k];
        __nv_bfloat16 h, l;
        split_bf16(v, h, l);
        o = (j >= DR && j < 2 * DR) ? l : h;
    }
    dst[idx] = o;
}

// ---------------- dt slice: dbl[:, :25] -> tight [Ah(25)|Ah(25)|Al(25)|0(53)] ----------------
__global__ void cvt_dt(const float* __restrict__ dbl, __nv_bfloat16* __restrict__ dst) {
    int idx = blockIdx.x * blockDim.x + threadIdx.x;
    if (idx >= TOK * K3_DT) return;
    int j = idx % K3_DT, r = idx / K3_DT;
    __nv_bfloat16 o = __float2bfloat16(0.f);
    if (j < 3 * DR) {
        int k = j % DR;
        float v = dbl[(size_t)r * XPO + k];
        __nv_bfloat16 h, l;
        split_bf16(v, h, l);
        o = (j >= 2 * DR) ? l : h;
    }
    dst[idx] = o;
}

// ---------------- layernorm fused with split, 2-wide (Kp=448 layout) ----------------
__global__ void ln_split(const float* __restrict__ x, const float* __restrict__ g,
                         const float* __restrict__ beta, __nv_bfloat16* __restrict__ a3) {
    int t = blockIdx.x;
    const float* xr = x + (size_t)t * DM;
    float s = 0.f, s2 = 0.f;
    for (int i = threadIdx.x; i < DM; i += 128) {
        float v = xr[i]; s += v; s2 += v * v;
    }
    #pragma unroll
    for (int o = 16; o; o >>= 1) {
        s  += __shfl_down_sync(0xffffffffu, s,  o);
        s2 += __shfl_down_sync(0xffffffffu, s2, o);
    }
    __shared__ float sh[2][4];
    __shared__ float mu_s, rs_s;
    int w = threadIdx.x >> 5, ln = threadIdx.x & 31;
    if (ln == 0) { sh[0][w] = s; sh[1][w] = s2; }
    __syncthreads();
    if (threadIdx.x == 0) {
        float S  = sh[0][0] + sh[0][1] + sh[0][2] + sh[0][3];
        float S2 = sh[1][0] + sh[1][1] + sh[1][2] + sh[1][3];
        float mu = S / DM;
        float var = S2 / DM - mu * mu;
        mu_s = mu;
        rs_s = rsqrtf(var + 1e-5f);
    }
    __syncthreads();
    float mu = mu_s, rs = rs_s;
    uint32_t* row = reinterpret_cast<uint32_t*>(a3 + (size_t)t * (3 * KP_IN));
    for (int p = threadIdx.x; p < KP_IN / 2; p += 128) {
        int i = p * 2;
        uint32_t ph, pl;
        if (i < DM) {
            float2 xv = *reinterpret_cast<const float2*>(xr + i);
            float2 gv = *reinterpret_cast<const float2*>(g + i);
            float2 bv = *reinterpret_cast<const float2*>(beta + i);
            float v0 = (xv.x - mu) * rs * gv.x + bv.x;
            float v1 = (xv.y - mu) * rs * gv.y + bv.y;
            __nv_bfloat16 h0, l0, h1, l1;
            split_bf16(v0, h0, l0);
            split_bf16(v1, h1, l1);
            ph = pack2(h0, h1);
            pl = pack2(l0, l1);
        } else { ph = 0u; pl = 0u; }
        row[p] = ph;
        row[KP_IN / 2 + p] = ph;
        row[KP_IN + p] = pl;
    }
}

// ---------------- conv+SiLU fused with split, 2-wide (Kp=832) ----------------
__global__ void conv_silu_split(const float* __restrict__ xz, const float* __restrict__ cw,
                                const float* __restrict__ cb, float* __restrict__ xc,
                                __nv_bfloat16* __restrict__ a3) {
    int idx = blockIdx.x * blockDim.x + threadIdx.x;
    if (idx >= TOK * (KP_XP / 2)) return;
    int p = idx % (KP_XP / 2);
    int r = idx / (KP_XP / 2);
    int d = p * 2;
    uint32_t* row = reinterpret_cast<uint32_t*>(a3 + (size_t)r * (3 * KP_XP));
    if (d >= DI) {
        row[p] = 0u; row[KP_XP / 2 + p] = 0u; row[KP_XP + p] = 0u;
        return;
    }
    int l = r % SEQ;
    int b = r / SEQ;
    const float* base = xz + (size_t)(b * SEQ) * (2 * DI) + d;
    float4 w0 = *reinterpret_cast<const float4*>(cw + d * DC);
    float4 w1 = *reinterpret_cast<const float4*>(cw + d * DC + 4);
    float2 cbv = *reinterpret_cast<const float2*>(cb + d);
    float a0 = cbv.x, a1 = cbv.y;
    const float wa0[4] = {w0.x, w0.y, w0.z, w0.w};
    const float wa1[4] = {w1.x, w1.y, w1.z, w1.w};
    #pragma unroll
    for (int j = 0; j < DC; j++) {
        int ls = l - (DC - 1) + j;
        if (ls >= 0) {
            float2 xv = *reinterpret_cast<const float2*>(base + (size_t)ls * (2 * DI));
            a0 += wa0[j] * xv.x;
            a1 += wa1[j] * xv.y;
        }
    }
    float v0 = a0 / (1.f + __expf(-a0));
    float v1 = a1 / (1.f + __expf(-a1));
    *reinterpret_cast<float2*>(xc + (size_t)r * DI + d) = make_float2(v0, v1);
    __nv_bfloat16 h0, l0, h1, l1;
    split_bf16(v0, h0, l0);
    split_bf16(v1, h1, l1);
    uint32_t ph = pack2(h0, h1), pl = pack2(l0, l1);
    row[p] = ph; row[KP_XP / 2 + p] = ph; row[KP_XP + p] = pl;
}

// ---------------- selective scan 2-wide, writes gated y as split (Kp=832) ----------------
__global__ void scan_split(const float* __restrict__ dt, const float* __restrict__ u,
                           const float* __restrict__ dbl, const float* __restrict__ xz,
                           const float* __restrict__ A_log, const float* __restrict__ Dp,
                           __nv_bfloat16* __restrict__ a3) {
    int idx = blockIdx.x * blockDim.x + threadIdx.x;
    if (idx >= BATCH * (KP_XP / 2)) return;
    int p = idx % (KP_XP / 2);
    int b = idx / (KP_XP / 2);
    int d = p * 2;
    size_t tok0 = (size_t)b * SEQ;
    if (d >= DI) {
        for (int l = 0; l < SEQ; l++) {
            uint32_t* row = reinterpret_cast<uint32_t*>(a3 + (tok0 + l) * (3 * KP_XP));
            row[p] = 0u; row[KP_XP / 2 + p] = 0u; row[KP_XP + p] = 0u;
        }
        return;
    }
    float Aa[2][DS];
    #pragma unroll
    for (int n = 0; n < DS; n++) {
        Aa[0][n] = -__expf(A_log[d * DS + n]);
        Aa[1][n] = -__expf(A_log[(d + 1) * DS + n]);
    }
    float2 Dv = *reinterpret_cast<const float2*>(Dp + d);
    float h0[DS], h1[DS];
    #pragma unroll
    for (int n = 0; n < DS; n++) { h0[n] = 0.f; h1[n] = 0.f; }
    for (int l = 0; l < SEQ; l++) {
        size_t t = tok0 + l;
        float2 dtv = *reinterpret_cast<const float2*>(dt + t * DI + d);
        float2 uv  = *reinterpret_cast<const float2*>(u + t * DI + d);
        const float* rb = dbl + t * XPO;
        float dtu0 = dtv.x * uv.x, dtu1 = dtv.y * uv.y;
        float y0 = 0.f, y1 = 0.f;
        #pragma unroll
        for (int n = 0; n < DS; n++) {
            float Bn = rb[DR + n], Cn = rb[DR + DS + n];
            float e0 = __expf(dtv.x * Aa[0][n]);
            float e1 = __expf(dtv.y * Aa[1][n]);
            h0[n] = e0 * h0[n] + dtu0 * Bn;
            h1[n] = e1 * h1[n] + dtu1 * Bn;
            y0 += h0[n] * Cn;
            y1 += h1[n] * Cn;
        }
        float2 zv = *reinterpret_cast<const float2*>(xz + t * (2 * DI) + DI + d);
        y0 += uv.x * Dv.x;
        y1 += uv.y * Dv.y;
        float v0 = y0 * (zv.x / (1.f + __expf(-zv.x)));
        float v1 = y1 * (zv.y / (1.f + __expf(-zv.y)));
        __nv_bfloat16 hh0, ll0, hh1, ll1;
        split_bf16(v0, hh0, ll0);
        split_bf16(v1, hh1, ll1);
        uint32_t ph = pack2(hh0, hh1), pl = pack2(ll0, ll1);
        uint32_t* row = reinterpret_cast<uint32_t*>(a3 + t * (3 * KP_XP));
        row[p] = ph; row[KP_XP / 2 + p] = ph; row[KP_XP + p] = pl;
    }
}

// ---------------- classifier ----------------
__global__ void cls_kernel(const float* __restrict__ x, const float* __restrict__ w,
                           const float* __restrict__ bias, float* __restrict__ out) {
    int b = blockIdx.x;
    const float* xr = x + (size_t)b * FLAT;
    float a0 = 0.f, a1 = 0.f, a2 = 0.f;
    for (int i = threadIdx.x; i < FLAT; i += 256) {
        float v = xr[i];
        a0 += v * w[i];
        a1 += v * w[FLAT + i];
        a2 += v * w[2 * FLAT + i];
    }
    #pragma unroll
    for (int o = 16; o; o >>= 1) {
        a0 += __shfl_down_sync(0xffffffffu, a0, o);
        a1 += __shfl_down_sync(0xffffffffu, a1, o);
        a2 += __shfl_down_sync(0xffffffffu, a2, o);
    }
    __shared__ float sh[3][8];
    int wi = threadIdx.x >> 5, ln = threadIdx.x & 31;
    if (ln == 0) { sh[0][wi] = a0; sh[1][wi] = a1; sh[2][wi] = a2; }
    __syncthreads();
    if (threadIdx.x == 0) {
        float l0 = bias[0], l1 = bias[1], l2 = bias[2];
        for (int k = 0; k < 8; k++) { l0 += sh[0][k]; l1 += sh[1][k]; l2 += sh[2][k]; }
        float m = fmaxf(l0, fmaxf(l1, l2));
        float e0 = expf(l0 - m), e1 = expf(l1 - m), e2 = expf(l2 - m);
        float inv = 1.f / (e0 + e1 + e2);
        out[b * 3 + 0] = e0 * inv;
        out[b * 3 + 1] = e1 * inv;
        out[b * 3 + 2] = e2 * inv;
    }
}

// ---------------- host launch ----------------
#define MMA_SMEM 98304

extern "C" void kernel_launch(void* const* d_in, const int* in_sizes, int n_in,
                              void* d_out, int out_size) {
    const float* x_in   = (const float*)d_in[0];
    const float* ln_g   = (const float*)d_in[1];
    const float* ln_b   = (const float*)d_in[2];
    const float* inp_w  = (const float*)d_in[3];
    const float* conv_w = (const float*)d_in[4];
    const float* conv_b = (const float*)d_in[5];
    const float* xp_w   = (const float*)d_in[6];
    const float* dt_w   = (const float*)d_in[7];
    const float* dt_b   = (const float*)d_in[8];
    const float* A_log  = (const float*)d_in[9];
    const float* Dp     = (const float*)d_in[10];
    const float* out_w  = (const float*)d_in[11];
    const float* cls_w  = (const float*)d_in[12];
    const float* cls_b  = (const float*)d_in[13];
    float* out = (float*)d_out;

    float *p_xz, *p_xc, *p_dbl, *p_dt, *p_x;
    __nv_bfloat16 *p_a3, *p_adt, *p_b3;
    cudaGetSymbolAddress((void**)&p_xz,  g_xz);
    cudaGetSymbolAddress((void**)&p_xc,  g_xc);
    cudaGetSymbolAddress((void**)&p_dbl, g_dbl);
    cudaGetSymbolAddress((void**)&p_dt,  g_dt);
    cudaGetSymbolAddress((void**)&p_x,   g_x);
    cudaGetSymbolAddress((void**)&p_a3,  g_a3);
    cudaGetSymbolAddress((void**)&p_adt, g_adt);
    cudaGetSymbolAddress((void**)&p_b3,  g_b3);

    cudaFuncSetAttribute(mma_gemm, cudaFuncAttributeMaxDynamicSharedMemorySize, MMA_SMEM);

    const int MB = TOK / 128;  // 290
    // supertile group sizes: ~256 CTAs per group
    const int NT_IN = NP_IN / 128, GM_IN = 20;    // 13 * 20 = 260
    const int NT_XP = NP_XP / 128, GM_XP = MB;    // single n-tile: plain
    const int NT_DT = NP_DT / 128, GM_DT = 36;    // 7 * 36 = 252
    const int NT_OUT = NP_OUT / 128, GM_OUT = 64; // 4 * 64 = 256

    for (int i = 0; i < NB; i++) {
        const float* src = (i == 0) ? x_in : p_x;
        ln_split<<<TOK, 128>>>(src, ln_g + i * DM, ln_b + i * DM, p_a3);

        // ---- in_proj
        cvt_w3<<<(NP_IN * KP_IN + 255) / 256, 256>>>(inp_w + (size_t)i * 2 * DI * DM,
                                                     2 * DI, DM, NP_IN, KP_IN, p_b3);
        mma_gemm<<<MB * NT_IN, 256, MMA_SMEM>>>(p_a3, p_b3, 3 * KP_IN,
                                                p_xz, 2 * DI, 2 * DI, nullptr, 0,
                                                MB, NT_IN, GM_IN);

        // conv + SiLU + split (2-wide)
        conv_silu_split<<<(TOK * (KP_XP / 2) + 255) / 256, 256>>>(
            p_xz, conv_w + (size_t)i * DI * DC, conv_b + (size_t)i * DI, p_xc, p_a3);

        // ---- x_proj
        cvt_w3<<<(NP_XP * KP_XP + 255) / 256, 256>>>(xp_w + (size_t)i * XPO * DI,
                                                     XPO, DI, NP_XP, KP_XP, p_b3);
        mma_gemm<<<MB * NT_XP, 256, MMA_SMEM>>>(p_a3, p_b3, 3 * KP_XP,
                                                p_dbl, XPO, XPO, nullptr, 0,
                                                MB, NT_XP, GM_XP);

        // ---- dt_proj (tight K3=128)
        cvt_dt<<<(TOK * K3_DT + 255) / 256, 256>>>(p_dbl, p_adt);
        cvt_wdt<<<(NP_DT * K3_DT + 255) / 256, 256>>>(dt_w + (size_t)i * DI * DR, p_b3);
        mma_gemm<<<MB * NT_DT, 256, MMA_SMEM>>>(p_adt, p_b3, K3_DT,
                                                p_dt, DI, DI, dt_b + (size_t)i * DI, 1,
                                                MB, NT_DT, GM_DT);

        // scan + gate + split (2-wide)
        scan_split<<<(BATCH * (KP_XP / 2) + 127) / 128, 128>>>(
            p_dt, p_xc, p_dbl, p_xz,
            A_log + (size_t)i * DI * DS, Dp + (size_t)i * DI, p_a3);

        // ---- out_proj
        cvt_w3<<<(NP_OUT * KP_OUT + 255) / 256, 256>>>(out_w + (size_t)i * DM * DI,
                                                       DM, DI, NP_OUT, KP_OUT, p_b3);
        mma_gemm<<<MB * NT_OUT, 256, MMA_SMEM>>>(p_a3, p_b3, 3 * KP_OUT,
                                                 p_x, DM, DM, nullptr, 0,
                                                 MB, NT_OUT, GM_OUT);
    }

    cls_kernel<<<BATCH, 256>>>(p_x, cls_w, cls_b, out);
}